// round 11
// baseline (speedup 1.0000x reference)
#include <cuda_runtime.h>
#include <cuda_bf16.h>
#include <math.h>

// Problem dims
#define BB 16
#define TT 512
#define II 256
#define HH 512
#define MM 2048
#define DD 64
#define NHD 4
#define OO 256
#define G4H 2048  // 4*H
#define EPSV 1e-8f

#define NBLK 128  // persistent LSTM grid (<= SM count -> co-resident)

// LSTM dynamic smem layout
#define HS2_BYTES  (HH * 8 * 8)        // 32768: h[k][b] as ull pairs
#define PART_BYTES (16 * 258 * 4)      // 16512: partials, padded stride
#define LSTM_SMEM  (HS2_BYTES + PART_BYTES)  // 49280 (> 48KB static -> dynamic)

typedef unsigned long long ull;

// ---------------- scratch (static device globals; no runtime alloc) ------------
__device__ float g_pregates[(size_t)BB * TT * G4H];   // 64 MB, row r = b*T+t
__device__ float g_hbuf[2][HH * BB];                  // [buf][k*16+b], double buffered
__device__ float g_combined[(size_t)BB * TT * (HH + NHD * DD)];  // [8192][768]
__device__ float g_keys[(size_t)BB * TT * NHD * DD];  // [32768][64]
__device__ float g_sims[(size_t)BB * TT * NHD * MM];  // 256 MB, [32768][2048]
__device__ float g_WhhT[HH * G4H];                    // [512][2048]
__device__ float g_memnorm[MM];
__device__ unsigned g_arrive[NBLK];                   // symmetric flag barrier slots

// ---------------- helpers ----------------
__device__ __forceinline__ float sigmoidf_(float x) {
    return 1.0f / (1.0f + __expf(-x));
}

__device__ __forceinline__ ull packf2(float a, float b) {
    ull r;
    asm("mov.b64 %0, {%1, %2};" : "=l"(r) : "f"(a), "f"(b));
    return r;
}
__device__ __forceinline__ void fma2(ull& d, ull a, ull b) {
    asm("fma.rn.f32x2 %0, %1, %2, %0;" : "+l"(d) : "l"(a), "l"(b));
}

__device__ __forceinline__ unsigned f2tf(float f) {
    unsigned r;
    asm("cvt.rna.tf32.f32 %0, %1;" : "=r"(r) : "f"(f));
    return r;
}

__device__ __forceinline__ void mma_tf32(float* c, const unsigned* a, const unsigned* b) {
    asm volatile(
        "mma.sync.aligned.m16n8k8.row.col.f32.tf32.tf32.f32 "
        "{%0,%1,%2,%3}, {%4,%5,%6,%7}, {%8,%9}, {%0,%1,%2,%3};"
        : "+f"(c[0]), "+f"(c[1]), "+f"(c[2]), "+f"(c[3])
        : "r"(a[0]), "r"(a[1]), "r"(a[2]), "r"(a[3]), "r"(b[0]), "r"(b[1]));
}

// One-hop symmetric grid barrier. Each block release-stores epoch e into its
// own slot; all blocks poll all NBLK slots in parallel with acquire loads.
// Monotonic flags + wraparound-safe >= compare avoid the race where a fast
// block advances to e+1 before a slow block finishes polling for e.
// Cross-block data reads elsewhere use __ldcg (L1 bypass), so no L1 flush
// (threadfence/CCTL.IVALL) is needed; acquire/release provide ordering.
// Flags are zeroed per launch via cudaMemsetAsync -> epochs deterministic
// across CUDA-graph replays.
__device__ __forceinline__ void grid_bar3(unsigned e, int tid, int bid) {
    __syncthreads();
    if (tid == 0) {
        asm volatile("st.release.gpu.global.u32 [%0], %1;"
                     :: "l"(g_arrive + bid), "r"(e) : "memory");
    }
    if (tid < NBLK) {
        unsigned v;
        do {
            asm volatile("ld.acquire.gpu.global.u32 %0, [%1];"
                         : "=r"(v) : "l"(g_arrive + tid) : "memory");
        } while ((int)(v - e) < 0);
    }
    __syncthreads();
}

// ---------------- small prep kernels ----------------
__global__ void transpose_whh_kernel(const float* __restrict__ W_hh) {
    int idx = blockIdx.x * 256 + threadIdx.x;  // total 2048*512
    int g = idx & (G4H - 1);
    int k = idx >> 11;
    g_WhhT[k * G4H + g] = W_hh[g * HH + k];
}

__global__ void memnorm_kernel(const float* __restrict__ memory) {
    __shared__ float s[64];
    int m = blockIdx.x;
    float v = memory[m * DD + threadIdx.x];
    s[threadIdx.x] = v * v;
    __syncthreads();
    for (int o = 32; o > 0; o >>= 1) {
        if (threadIdx.x < o) s[threadIdx.x] += s[threadIdx.x + o];
        __syncthreads();
    }
    if (threadIdx.x == 0) g_memnorm[m] = sqrtf(s[0]);
}

// ---------------- tf32 tensor-core GEMM ----------------
// C[m][n] = sum_k A[m*lda+k] * (BT ? B[n*ldb+k] : B[k*ldb+n]) + bias1[n] + bias2[n]
// Block tile 128 x BN, BK=16, double buffered. 8 warps in 4(m) x 2(n); warp tile
// 32 x (BN/2); mma.sync m16n8k8 tf32. M%128==0, N%BN==0, K%16==0, lda/ldb%4==0.
// REMAP: row m writes to C[(m>>2)*768 + 512 + (m&3)*64 + n] (reads->combined fusion).
template <bool BT, int BN, bool REMAP>
__global__ void __launch_bounds__(256) tgemm(
    const float* __restrict__ A, const float* __restrict__ B, float* __restrict__ C,
    int M, int N, int K, int lda, int ldb, int ldc,
    const float* __restrict__ bias1, const float* __restrict__ bias2)
{
    constexpr int WN = BN / 2;    // warp n extent: 64 or 32
    constexpr int NT = WN / 8;    // n-tiles per warp: 8 or 4
    __shared__ unsigned As[2][16][132];
    __shared__ unsigned Bs[2][16][BN + 4];

    int tid = threadIdx.x;
    int wid = tid >> 5, lane = tid & 31;
    int wm = (wid >> 1) * 32;     // 0,32,64,96
    int wn = (wid & 1) * WN;
    int m0 = blockIdx.y * 128;
    int n0 = blockIdx.x * BN;
    int g = lane >> 2, tg = lane & 3;

    float acc[2][NT][4];
#pragma unroll
    for (int i = 0; i < 2; i++)
#pragma unroll
        for (int j = 0; j < NT; j++)
#pragma unroll
            for (int e = 0; e < 4; e++) acc[i][j][e] = 0.0f;

    // A loader: row a_r = tid>>1 (0..127), k offset ak = (tid&1)*8, 2 float4/stage
    int a_r = tid >> 1;
    int ak = (tid & 1) * 8;
    const float* Aptr = A + (size_t)(m0 + a_r) * lda + ak;

    // B loader
    const float* Bptr;
    int bn4 = 0, bk_nn = 0;
    if (BT) {
        // B is [N][K]; rows = n. Same pattern as A. (BN==128 assumed)
        Bptr = B + (size_t)(n0 + a_r) * ldb + ak;
    } else {
        // B is [K][N]; 16 x BN floats/stage; BN==64 -> 1 float4/thread
        bk_nn = tid >> 4;             // 0..15
        bn4 = (tid & 15) * 4;         // 0..60
        Bptr = B + (size_t)bk_nn * ldb + n0 + bn4;
    }

    int KT = K >> 4;

    // prologue: stage 0
    {
        float4 a0 = *(const float4*)Aptr;
        float4 a1 = *(const float4*)(Aptr + 4);
        As[0][ak + 0][a_r] = f2tf(a0.x); As[0][ak + 1][a_r] = f2tf(a0.y);
        As[0][ak + 2][a_r] = f2tf(a0.z); As[0][ak + 3][a_r] = f2tf(a0.w);
        As[0][ak + 4][a_r] = f2tf(a1.x); As[0][ak + 5][a_r] = f2tf(a1.y);
        As[0][ak + 6][a_r] = f2tf(a1.z); As[0][ak + 7][a_r] = f2tf(a1.w);
        if (BT) {
            float4 b0 = *(const float4*)Bptr;
            float4 b1 = *(const float4*)(Bptr + 4);
            Bs[0][ak + 0][a_r] = f2tf(b0.x); Bs[0][ak + 1][a_r] = f2tf(b0.y);
            Bs[0][ak + 2][a_r] = f2tf(b0.z); Bs[0][ak + 3][a_r] = f2tf(b0.w);
            Bs[0][ak + 4][a_r] = f2tf(b1.x); Bs[0][ak + 5][a_r] = f2tf(b1.y);
            Bs[0][ak + 6][a_r] = f2tf(b1.z); Bs[0][ak + 7][a_r] = f2tf(b1.w);
        } else {
            float4 b0 = *(const float4*)Bptr;
            Bs[0][bk_nn][bn4 + 0] = f2tf(b0.x); Bs[0][bk_nn][bn4 + 1] = f2tf(b0.y);
            Bs[0][bk_nn][bn4 + 2] = f2tf(b0.z); Bs[0][bk_nn][bn4 + 3] = f2tf(b0.w);
        }
    }
    __syncthreads();

    for (int kt = 0; kt < KT; kt++) {
        int cur = kt & 1;
        float4 pa0, pa1, pb0, pb1;
        bool has_next = (kt + 1 < KT);
        if (has_next) {
            pa0 = *(const float4*)(Aptr + (kt + 1) * 16);
            pa1 = *(const float4*)(Aptr + (kt + 1) * 16 + 4);
            if (BT) {
                pb0 = *(const float4*)(Bptr + (kt + 1) * 16);
                pb1 = *(const float4*)(Bptr + (kt + 1) * 16 + 4);
            } else {
                pb0 = *(const float4*)(Bptr + (size_t)(kt + 1) * 16 * ldb);
            }
        }

#pragma unroll
        for (int ks = 0; ks < 2; ks++) {
            int kb = ks * 8;
            unsigned af[2][4];
#pragma unroll
            for (int mt = 0; mt < 2; mt++) {
                int row = wm + mt * 16;
                af[mt][0] = As[cur][kb + tg][row + g];
                af[mt][1] = As[cur][kb + tg][row + g + 8];
                af[mt][2] = As[cur][kb + tg + 4][row + g];
                af[mt][3] = As[cur][kb + tg + 4][row + g + 8];
            }
            unsigned bf[NT][2];
#pragma unroll
            for (int nt = 0; nt < NT; nt++) {
                bf[nt][0] = Bs[cur][kb + tg][wn + nt * 8 + g];
                bf[nt][1] = Bs[cur][kb + tg + 4][wn + nt * 8 + g];
            }
#pragma unroll
            for (int mt = 0; mt < 2; mt++)
#pragma unroll
                for (int nt = 0; nt < NT; nt++)
                    mma_tf32(acc[mt][nt], af[mt], bf[nt]);
        }

        if (has_next) {
            int nxt = cur ^ 1;
            As[nxt][ak + 0][a_r] = f2tf(pa0.x); As[nxt][ak + 1][a_r] = f2tf(pa0.y);
            As[nxt][ak + 2][a_r] = f2tf(pa0.z); As[nxt][ak + 3][a_r] = f2tf(pa0.w);
            As[nxt][ak + 4][a_r] = f2tf(pa1.x); As[nxt][ak + 5][a_r] = f2tf(pa1.y);
            As[nxt][ak + 6][a_r] = f2tf(pa1.z); As[nxt][ak + 7][a_r] = f2tf(pa1.w);
            if (BT) {
                Bs[nxt][ak + 0][a_r] = f2tf(pb0.x); Bs[nxt][ak + 1][a_r] = f2tf(pb0.y);
                Bs[nxt][ak + 2][a_r] = f2tf(pb0.z); Bs[nxt][ak + 3][a_r] = f2tf(pb0.w);
                Bs[nxt][ak + 4][a_r] = f2tf(pb1.x); Bs[nxt][ak + 5][a_r] = f2tf(pb1.y);
                Bs[nxt][ak + 6][a_r] = f2tf(pb1.z); Bs[nxt][ak + 7][a_r] = f2tf(pb1.w);
            } else {
                Bs[nxt][bk_nn][bn4 + 0] = f2tf(pb0.x); Bs[nxt][bk_nn][bn4 + 1] = f2tf(pb0.y);
                Bs[nxt][bk_nn][bn4 + 2] = f2tf(pb0.z); Bs[nxt][bk_nn][bn4 + 3] = f2tf(pb0.w);
            }
            __syncthreads();
        }
    }

    // epilogue
#pragma unroll
    for (int mt = 0; mt < 2; mt++) {
        int r0 = m0 + wm + mt * 16 + g;
#pragma unroll
        for (int nt = 0; nt < NT; nt++) {
            int cc = n0 + wn + nt * 8 + tg * 2;
            float bv0 = 0.0f, bv1 = 0.0f;
            if (bias1) { bv0 += bias1[cc]; bv1 += bias1[cc + 1]; }
            if (bias2) { bv0 += bias2[cc]; bv1 += bias2[cc + 1]; }
            float2 v0 = make_float2(acc[mt][nt][0] + bv0, acc[mt][nt][1] + bv1);
            float2 v1 = make_float2(acc[mt][nt][2] + bv0, acc[mt][nt][3] + bv1);
            if (REMAP) {
                int ra = r0, rb2 = r0 + 8;
                size_t o0 = (size_t)(ra >> 2) * 768 + 512 + (ra & 3) * 64 + cc;
                size_t o1 = (size_t)(rb2 >> 2) * 768 + 512 + (rb2 & 3) * 64 + cc;
                *(float2*)&C[o0] = v0;
                *(float2*)&C[o1] = v1;
            } else {
                *(float2*)&C[(size_t)r0 * ldc + cc] = v0;
                *(float2*)&C[(size_t)(r0 + 8) * ldc + cc] = v1;
            }
        }
    }
}

// ---------------- persistent LSTM kernel ----------------
// 128 blocks x 256 threads. Block bid owns h-cols j = bid*4 .. bid*4+3, i.e.
// 16 gate columns col(c) = (c>>2)*512 + bid*4 + (c&3).  One one-hop flag
// barrier per step. W_hh^T in registers (32 floats/thread). h via global
// double buffer in [k][b] layout, read with __ldcg (L1 bypass -> no fence
// needed for coherence). Gate GEMM uses packed f32x2 FMA over batch pairs.
// Reduce+activation merged into one phase (2 syncthreads/step, no gsm).
__global__ void __launch_bounds__(256) lstm_kernel() {
    extern __shared__ __align__(16) char dynsm[];
    ull*   hs2     = (ull*)dynsm;                              // h[k][b] pairs, 32KB
    float* part_sm = (float*)(dynsm + HS2_BYTES);              // [c][ks*16+b], stride 258

    int tid = threadIdx.x;
    int bid = blockIdx.x;

    int ks = tid >> 4;       // 0..15 -> k range [ks*32, ks*32+32)
    int c  = tid & 15;       // 0..15 gate-col within block
    int col = (c >> 2) * 512 + bid * 4 + (c & 3);

    int uj = tid >> 4;       // 0..3 local h col (tid<64 path)
    int ub = tid & 15;

    float wreg[32];
#pragma unroll
    for (int kk = 0; kk < 32; kk++)
        wreg[kk] = g_WhhT[(size_t)(ks * 32 + kk) * G4H + col];

    if (tid < 64) g_hbuf[1][bid * 64 + tid] = 0.0f;
    float creg = 0.0f;

    unsigned e = 1;          // flags memset to 0 each launch
    grid_bar3(e, tid, bid);  // zero-init of hbuf visible everywhere
    e++;

    for (int t = 0; t < TT; t++) {
        int rbuf = (t & 1) ^ 1;
        int wbuf = t & 1;

        // prefetch this step's 4 pregate values (independent of h)
        float pre[4];
        if (tid < 64) {
            size_t base = ((size_t)(ub * TT + t)) * G4H + bid * 4 + uj;
#pragma unroll
            for (int q = 0; q < 4; q++) pre[q] = g_pregates[base + q * 512];
        }

        // broadcast h into smem (32KB, coalesced float4, L1-bypass)
        {
            const float4* src = (const float4*)g_hbuf[rbuf];
            float4* dst = (float4*)hs2;
#pragma unroll
            for (int i = 0; i < 8; i++) dst[tid + i * 256] = __ldcg(&src[tid + i * 256]);
        }
        __syncthreads();

        // partial gate GEMM: this thread: col, k in [ks*32, ks*32+32), all 16 batches
        ull acc[8];
#pragma unroll
        for (int p = 0; p < 8; p++) acc[p] = 0ULL;
#pragma unroll
        for (int kk = 0; kk < 32; kk++) {
            int k = ks * 32 + kk;
            float w = wreg[kk];
            ull w2 = packf2(w, w);
            const ulonglong2* hp = (const ulonglong2*)(hs2 + (size_t)k * 8);
            ulonglong2 h01 = hp[0];
            ulonglong2 h23 = hp[1];
            ulonglong2 h45 = hp[2];
            ulonglong2 h67 = hp[3];
            fma2(acc[0], h01.x, w2);
            fma2(acc[1], h01.y, w2);
            fma2(acc[2], h23.x, w2);
            fma2(acc[3], h23.y, w2);
            fma2(acc[4], h45.x, w2);
            fma2(acc[5], h45.y, w2);
            fma2(acc[6], h67.x, w2);
            fma2(acc[7], h67.y, w2);
        }
        {
            ull* pp = (ull*)&part_sm[c * 258 + ks * 16];
#pragma unroll
            for (int p = 0; p < 8; p++) pp[p] = acc[p];
        }
        __syncthreads();

        // merged reduce + activation + state update (64 threads)
        if (tid < 64) {
            float gv[4];
#pragma unroll
            for (int q = 0; q < 4; q++) {
                float s = pre[q];
                int base = (q * 4 + uj) * 258 + ub;
#pragma unroll
                for (int k2 = 0; k2 < 16; k2++)
                    s += part_sm[base + k2 * 16];
                gv[q] = s;
            }
            float ig = sigmoidf_(gv[0]);
            float fg = sigmoidf_(gv[1]);
            float gg = tanhf(gv[2]);
            float og = sigmoidf_(gv[3]);
            creg = fg * creg + ig * gg;
            float hn = og * tanhf(creg);
            int j = bid * 4 + uj;
            g_hbuf[wbuf][j * 16 + ub] = hn;
            g_combined[((size_t)(ub * TT + t)) * 768 + j] = hn;
        }

        if (t < TT - 1) {        // last step's h is read by nobody
            grid_bar3(e, tid, bid);
            e++;
        }
    }
}

// ---------------- softmax over memory slots (with cosine scaling) --------------
__global__ void __launch_bounds__(256) softmax_kernel() {
    __shared__ float red[256];
    __shared__ float s_kn;
    int p = blockIdx.x;          // 0..32767 (= (b*T+t)*4 + n)
    int tid = threadIdx.x;

    float kv = 0.0f;
    if (tid < DD) {
        float k = g_keys[(size_t)p * DD + tid];
        kv = k * k;
    }
    red[tid] = kv;
    __syncthreads();
    for (int o = 128; o > 0; o >>= 1) {
        if (tid < o) red[tid] += red[tid + o];
        __syncthreads();
    }
    if (tid == 0) s_kn = sqrtf(red[0]);
    __syncthreads();
    float kn = s_kn;
    __syncthreads();

    float v[8];
    float mx = -3.0e38f;
#pragma unroll
    for (int i = 0; i < 8; i++) {
        int m = tid + i * 256;
        float s = g_sims[(size_t)p * MM + m];
        s = s / fmaxf(kn * g_memnorm[m], EPSV);
        v[i] = s;
        mx = fmaxf(mx, s);
    }
    red[tid] = mx;
    __syncthreads();
    for (int o = 128; o > 0; o >>= 1) {
        if (tid < o) red[tid] = fmaxf(red[tid], red[tid + o]);
        __syncthreads();
    }
    mx = red[0];
    __syncthreads();

    float sum = 0.0f;
#pragma unroll
    for (int i = 0; i < 8; i++) {
        v[i] = __expf(v[i] - mx);
        sum += v[i];
    }
    red[tid] = sum;
    __syncthreads();
    for (int o = 128; o > 0; o >>= 1) {
        if (tid < o) red[tid] += red[tid + o];
        __syncthreads();
    }
    float inv = 1.0f / red[0];
#pragma unroll
    for (int i = 0; i < 8; i++) {
        int m = tid + i * 256;
        g_sims[(size_t)p * MM + m] = v[i] * inv;
    }
}

// ---------------- launch ----------------
extern "C" void kernel_launch(void* const* d_in, const int* in_sizes, int n_in,
                              void* d_out, int out_size) {
    const float* x      = (const float*)d_in[0];
    const float* memory = (const float*)d_in[1];
    const float* W_ih   = (const float*)d_in[2];
    const float* W_hh   = (const float*)d_in[3];
    const float* b_ih   = (const float*)d_in[4];
    const float* b_hh   = (const float*)d_in[5];
    const float* W_if   = (const float*)d_in[6];
    const float* b_if   = (const float*)d_in[7];
    const float* W_out  = (const float*)d_in[8];
    const float* b_out  = (const float*)d_in[9];
    float* out = (float*)d_out;

    float *pg, *comb, *keys, *sims;
    unsigned* arr;
    cudaGetSymbolAddress((void**)&pg, g_pregates);
    cudaGetSymbolAddress((void**)&comb, g_combined);
    cudaGetSymbolAddress((void**)&keys, g_keys);
    cudaGetSymbolAddress((void**)&sims, g_sims);
    cudaGetSymbolAddress((void**)&arr, g_arrive);

    // opt-in to >48KB dynamic smem for the LSTM kernel (attribute call, not an alloc)
    cudaFuncSetAttribute(lstm_kernel, cudaFuncAttributeMaxDynamicSharedMemorySize, LSTM_SMEM);

    // zero barrier flags (async memset node; graph-capturable, no allocation)
    cudaMemsetAsync(arr, 0, NBLK * sizeof(unsigned), 0);

    // prep
    transpose_whh_kernel<<<(G4H * HH) / 256, 256>>>(W_hh);
    memnorm_kernel<<<MM, 64>>>(memory);

    // pre-gates: [8192,2048] = x[8192,256] @ W_ih^T + (b_ih + b_hh)
    tgemm<true, 128, false><<<dim3(G4H / 128, (BB * TT) / 128), 256>>>(
        x, W_ih, pg, BB * TT, G4H, II, II, II, G4H, b_ih, b_hh);

    // sequential LSTM recurrence (persistent, 1 one-hop flag-barrier/step)
    lstm_kernel<<<NBLK, 256, LSTM_SMEM>>>();

    // keys: [8192,256] = hs(combined[:, :512], lda=768) @ W_if[:256]^T + b_if[:256]
    tgemm<true, 128, false><<<dim3(256 / 128, (BB * TT) / 128), 256>>>(
        comb, W_if, keys, BB * TT, NHD * DD, HH, 768, HH, NHD * DD, b_if, nullptr);

    // sims: [32768,2048] = keys[32768,64] @ memory^T
    tgemm<true, 128, false><<<dim3(MM / 128, (BB * TT * NHD) / 128), 256>>>(
        keys, memory, sims, BB * TT * NHD, MM, DD, DD, DD, MM, nullptr, nullptr);

    // cosine-scale + softmax (in place on sims)
    softmax_kernel<<<BB * TT * NHD, 256>>>();

    // reads: attn[32768,2048] @ memory[2048,64], epilogue writes straight into
    // combined[r][512 + n*64 + d] via REMAP (row m = r*4+n)
    tgemm<false, 64, true><<<dim3(1, (BB * TT * NHD) / 128), 256>>>(
        sims, memory, comb, BB * TT * NHD, DD, MM, MM, DD, 0, nullptr, nullptr);

    // out: [8192,256] = combined[8192,768] @ W_out^T + b_out
    tgemm<true, 128, false><<<dim3(OO / 128, (BB * TT) / 128), 256>>>(
        comb, W_out, out, BB * TT, OO, HH + NHD * DD, 768, 768, OO, b_out, nullptr);
}

// round 12
// speedup vs baseline: 1.8295x; 1.8295x over previous
#include <cuda_runtime.h>
#include <cuda_bf16.h>
#include <math.h>

// Problem dims
#define BB 16
#define TT 512
#define II 256
#define HH 512
#define MM 2048
#define DD 64
#define NHD 4
#define OO 256
#define G4H 2048  // 4*H
#define EPSV 1e-8f

#define NBLK 128  // persistent LSTM grid (<= SM count -> co-resident)

// LSTM dynamic smem layout
#define HS2_BYTES  (HH * 8 * 8)        // 32768: h[k][b] as ull pairs
#define PART_BYTES (16 * 258 * 4)      // 16512: partials, padded stride
#define LSTM_SMEM  (HS2_BYTES + PART_BYTES)  // 49280 (> 48KB static -> dynamic)

typedef unsigned long long ull;

// ---------------- scratch (static device globals; no runtime alloc) ------------
__device__ float g_pregates[(size_t)BB * TT * G4H];   // 64 MB, row r = b*T+t
__device__ float g_hbuf[2][HH * BB];                  // [buf][k*16+b], double buffered
__device__ float g_combined[(size_t)BB * TT * (HH + NHD * DD)];  // [8192][768]
__device__ float g_keys[(size_t)BB * TT * NHD * DD];  // [32768][64]
__device__ float g_sims[(size_t)BB * TT * NHD * MM];  // 256 MB, [32768][2048]
__device__ float g_WhhT[HH * G4H];                    // [512][2048]
__device__ float g_memnorm[MM];
__device__ volatile unsigned g_arrive[NBLK];          // flag barrier: per-block arrival
__device__ volatile unsigned g_release;               // flag barrier: release epoch

// ---------------- helpers ----------------
__device__ __forceinline__ float sigmoidf_(float x) {
    return 1.0f / (1.0f + __expf(-x));
}

__device__ __forceinline__ ull packf2(float a, float b) {
    ull r;
    asm("mov.b64 %0, {%1, %2};" : "=l"(r) : "f"(a), "f"(b));
    return r;
}
__device__ __forceinline__ void fma2(ull& d, ull a, ull b) {
    asm("fma.rn.f32x2 %0, %1, %2, %0;" : "+l"(d) : "l"(a), "l"(b));
}

__device__ __forceinline__ unsigned f2tf(float f) {
    unsigned r;
    asm("cvt.rna.tf32.f32 %0, %1;" : "=r"(r) : "f"(f));
    return r;
}

__device__ __forceinline__ void mma_tf32(float* c, const unsigned* a, const unsigned* b) {
    asm volatile(
        "mma.sync.aligned.m16n8k8.row.col.f32.tf32.tf32.f32 "
        "{%0,%1,%2,%3}, {%4,%5,%6,%7}, {%8,%9}, {%0,%1,%2,%3};"
        : "+f"(c[0]), "+f"(c[1]), "+f"(c[2]), "+f"(c[3])
        : "r"(a[0]), "r"(a[1]), "r"(a[2]), "r"(a[3]), "r"(b[0]), "r"(b[1]));
}

// Flag-based grid barrier (R9-measured design): one volatile store per block
// into a distinct slot, block 0 aggregates with 128 parallel pollers (distinct
// lines), publishes g_release; other blocks have ONE thread polling the single
// release word (L2-broadcast friendly). Consumer-side __threadfence() (gpu
// scope -> CCTL.IVALL) invalidates L1 so subsequent g_hbuf reads are coherent.
// Epochs are absolute (seeded from g_release at kernel entry) -> safe across
// CUDA-graph replays.
__device__ __forceinline__ void grid_bar2(unsigned e, int tid, int bid) {
    __syncthreads();
    if (tid == 0) {
        __threadfence();              // publish this block's global writes
        g_arrive[bid] = e;
    }
    if (bid == 0) {
        if (tid < NBLK) {
            while (g_arrive[tid] != e) { }
        }
        __syncthreads();
        if (tid == 0) g_release = e;
    } else {
        if (tid == 0) {
            while (g_release != e) { }
        }
    }
    if (tid == 0) __threadfence();    // acquire side: flush/invalidate L1
    __syncthreads();
}

// ---------------- small prep kernels ----------------
__global__ void transpose_whh_kernel(const float* __restrict__ W_hh) {
    int idx = blockIdx.x * 256 + threadIdx.x;  // total 2048*512
    int g = idx & (G4H - 1);
    int k = idx >> 11;
    g_WhhT[k * G4H + g] = W_hh[g * HH + k];
}

__global__ void memnorm_kernel(const float* __restrict__ memory) {
    __shared__ float s[64];
    int m = blockIdx.x;
    float v = memory[m * DD + threadIdx.x];
    s[threadIdx.x] = v * v;
    __syncthreads();
    for (int o = 32; o > 0; o >>= 1) {
        if (threadIdx.x < o) s[threadIdx.x] += s[threadIdx.x + o];
        __syncthreads();
    }
    if (threadIdx.x == 0) g_memnorm[m] = sqrtf(s[0]);
}

// ---------------- tf32 tensor-core GEMM ----------------
// C[m][n] = sum_k A[m*lda+k] * (BT ? B[n*ldb+k] : B[k*ldb+n]) + bias1[n] + bias2[n]
// Block tile 128 x BN, BK=16, double buffered. 8 warps in 4(m) x 2(n); warp tile
// 32 x (BN/2); mma.sync m16n8k8 tf32. M%128==0, N%BN==0, K%16==0, lda/ldb%4==0.
// REMAP: row m writes to C[(m>>2)*768 + 512 + (m&3)*64 + n] (reads->combined fusion).
template <bool BT, int BN, bool REMAP>
__global__ void __launch_bounds__(256) tgemm(
    const float* __restrict__ A, const float* __restrict__ B, float* __restrict__ C,
    int M, int N, int K, int lda, int ldb, int ldc,
    const float* __restrict__ bias1, const float* __restrict__ bias2)
{
    constexpr int WN = BN / 2;    // warp n extent: 64 or 32
    constexpr int NT = WN / 8;    // n-tiles per warp: 8 or 4
    __shared__ unsigned As[2][16][132];
    __shared__ unsigned Bs[2][16][BN + 4];

    int tid = threadIdx.x;
    int wid = tid >> 5, lane = tid & 31;
    int wm = (wid >> 1) * 32;     // 0,32,64,96
    int wn = (wid & 1) * WN;
    int m0 = blockIdx.y * 128;
    int n0 = blockIdx.x * BN;
    int g = lane >> 2, tg = lane & 3;

    float acc[2][NT][4];
#pragma unroll
    for (int i = 0; i < 2; i++)
#pragma unroll
        for (int j = 0; j < NT; j++)
#pragma unroll
            for (int e = 0; e < 4; e++) acc[i][j][e] = 0.0f;

    // A loader: row a_r = tid>>1 (0..127), k offset ak = (tid&1)*8, 2 float4/stage
    int a_r = tid >> 1;
    int ak = (tid & 1) * 8;
    const float* Aptr = A + (size_t)(m0 + a_r) * lda + ak;

    // B loader
    const float* Bptr;
    int bn4 = 0, bk_nn = 0;
    if (BT) {
        // B is [N][K]; rows = n. Same pattern as A. (BN==128 assumed)
        Bptr = B + (size_t)(n0 + a_r) * ldb + ak;
    } else {
        // B is [K][N]; 16 x BN floats/stage; BN==64 -> 1 float4/thread
        bk_nn = tid >> 4;             // 0..15
        bn4 = (tid & 15) * 4;         // 0..60
        Bptr = B + (size_t)bk_nn * ldb + n0 + bn4;
    }

    int KT = K >> 4;

    // prologue: stage 0
    {
        float4 a0 = *(const float4*)Aptr;
        float4 a1 = *(const float4*)(Aptr + 4);
        As[0][ak + 0][a_r] = f2tf(a0.x); As[0][ak + 1][a_r] = f2tf(a0.y);
        As[0][ak + 2][a_r] = f2tf(a0.z); As[0][ak + 3][a_r] = f2tf(a0.w);
        As[0][ak + 4][a_r] = f2tf(a1.x); As[0][ak + 5][a_r] = f2tf(a1.y);
        As[0][ak + 6][a_r] = f2tf(a1.z); As[0][ak + 7][a_r] = f2tf(a1.w);
        if (BT) {
            float4 b0 = *(const float4*)Bptr;
            float4 b1 = *(const float4*)(Bptr + 4);
            Bs[0][ak + 0][a_r] = f2tf(b0.x); Bs[0][ak + 1][a_r] = f2tf(b0.y);
            Bs[0][ak + 2][a_r] = f2tf(b0.z); Bs[0][ak + 3][a_r] = f2tf(b0.w);
            Bs[0][ak + 4][a_r] = f2tf(b1.x); Bs[0][ak + 5][a_r] = f2tf(b1.y);
            Bs[0][ak + 6][a_r] = f2tf(b1.z); Bs[0][ak + 7][a_r] = f2tf(b1.w);
        } else {
            float4 b0 = *(const float4*)Bptr;
            Bs[0][bk_nn][bn4 + 0] = f2tf(b0.x); Bs[0][bk_nn][bn4 + 1] = f2tf(b0.y);
            Bs[0][bk_nn][bn4 + 2] = f2tf(b0.z); Bs[0][bk_nn][bn4 + 3] = f2tf(b0.w);
        }
    }
    __syncthreads();

    for (int kt = 0; kt < KT; kt++) {
        int cur = kt & 1;
        float4 pa0, pa1, pb0, pb1;
        bool has_next = (kt + 1 < KT);
        if (has_next) {
            pa0 = *(const float4*)(Aptr + (kt + 1) * 16);
            pa1 = *(const float4*)(Aptr + (kt + 1) * 16 + 4);
            if (BT) {
                pb0 = *(const float4*)(Bptr + (kt + 1) * 16);
                pb1 = *(const float4*)(Bptr + (kt + 1) * 16 + 4);
            } else {
                pb0 = *(const float4*)(Bptr + (size_t)(kt + 1) * 16 * ldb);
            }
        }

#pragma unroll
        for (int ks = 0; ks < 2; ks++) {
            int kb = ks * 8;
            unsigned af[2][4];
#pragma unroll
            for (int mt = 0; mt < 2; mt++) {
                int row = wm + mt * 16;
                af[mt][0] = As[cur][kb + tg][row + g];
                af[mt][1] = As[cur][kb + tg][row + g + 8];
                af[mt][2] = As[cur][kb + tg + 4][row + g];
                af[mt][3] = As[cur][kb + tg + 4][row + g + 8];
            }
            unsigned bf[NT][2];
#pragma unroll
            for (int nt = 0; nt < NT; nt++) {
                bf[nt][0] = Bs[cur][kb + tg][wn + nt * 8 + g];
                bf[nt][1] = Bs[cur][kb + tg + 4][wn + nt * 8 + g];
            }
#pragma unroll
            for (int mt = 0; mt < 2; mt++)
#pragma unroll
                for (int nt = 0; nt < NT; nt++)
                    mma_tf32(acc[mt][nt], af[mt], bf[nt]);
        }

        if (has_next) {
            int nxt = cur ^ 1;
            As[nxt][ak + 0][a_r] = f2tf(pa0.x); As[nxt][ak + 1][a_r] = f2tf(pa0.y);
            As[nxt][ak + 2][a_r] = f2tf(pa0.z); As[nxt][ak + 3][a_r] = f2tf(pa0.w);
            As[nxt][ak + 4][a_r] = f2tf(pa1.x); As[nxt][ak + 5][a_r] = f2tf(pa1.y);
            As[nxt][ak + 6][a_r] = f2tf(pa1.z); As[nxt][ak + 7][a_r] = f2tf(pa1.w);
            if (BT) {
                Bs[nxt][ak + 0][a_r] = f2tf(pb0.x); Bs[nxt][ak + 1][a_r] = f2tf(pb0.y);
                Bs[nxt][ak + 2][a_r] = f2tf(pb0.z); Bs[nxt][ak + 3][a_r] = f2tf(pb0.w);
                Bs[nxt][ak + 4][a_r] = f2tf(pb1.x); Bs[nxt][ak + 5][a_r] = f2tf(pb1.y);
                Bs[nxt][ak + 6][a_r] = f2tf(pb1.z); Bs[nxt][ak + 7][a_r] = f2tf(pb1.w);
            } else {
                Bs[nxt][bk_nn][bn4 + 0] = f2tf(pb0.x); Bs[nxt][bk_nn][bn4 + 1] = f2tf(pb0.y);
                Bs[nxt][bk_nn][bn4 + 2] = f2tf(pb0.z); Bs[nxt][bk_nn][bn4 + 3] = f2tf(pb0.w);
            }
            __syncthreads();
        }
    }

    // epilogue
#pragma unroll
    for (int mt = 0; mt < 2; mt++) {
        int r0 = m0 + wm + mt * 16 + g;
#pragma unroll
        for (int nt = 0; nt < NT; nt++) {
            int cc = n0 + wn + nt * 8 + tg * 2;
            float bv0 = 0.0f, bv1 = 0.0f;
            if (bias1) { bv0 += bias1[cc]; bv1 += bias1[cc + 1]; }
            if (bias2) { bv0 += bias2[cc]; bv1 += bias2[cc + 1]; }
            float2 v0 = make_float2(acc[mt][nt][0] + bv0, acc[mt][nt][1] + bv1);
            float2 v1 = make_float2(acc[mt][nt][2] + bv0, acc[mt][nt][3] + bv1);
            if (REMAP) {
                int ra = r0, rb2 = r0 + 8;
                size_t o0 = (size_t)(ra >> 2) * 768 + 512 + (ra & 3) * 64 + cc;
                size_t o1 = (size_t)(rb2 >> 2) * 768 + 512 + (rb2 & 3) * 64 + cc;
                *(float2*)&C[o0] = v0;
                *(float2*)&C[o1] = v1;
            } else {
                *(float2*)&C[(size_t)r0 * ldc + cc] = v0;
                *(float2*)&C[(size_t)(r0 + 8) * ldc + cc] = v1;
            }
        }
    }
}

// ---------------- persistent LSTM kernel ----------------
// 128 blocks x 256 threads. Block bid owns h-cols j = bid*4 .. bid*4+3, i.e.
// 16 gate columns col(c) = (c>>2)*512 + bid*4 + (c&3).  One R9-style flag
// barrier per step. W_hh^T in registers (32 floats/thread). h via global
// double buffer in [k][b] layout. Gate GEMM uses packed f32x2 FMA over batch
// pairs. Reduce+activation merged (2 syncthreads/step, no gsm staging).
__global__ void __launch_bounds__(256) lstm_kernel() {
    extern __shared__ __align__(16) char dynsm[];
    ull*   hs2     = (ull*)dynsm;                              // h[k][b] pairs, 32KB
    float* part_sm = (float*)(dynsm + HS2_BYTES);              // [c][ks*16+b], stride 258

    int tid = threadIdx.x;
    int bid = blockIdx.x;

    int ks = tid >> 4;       // 0..15 -> k range [ks*32, ks*32+32)
    int c  = tid & 15;       // 0..15 gate-col within block
    int col = (c >> 2) * 512 + bid * 4 + (c & 3);

    int uj = tid >> 4;       // 0..3 local h col (tid<64 path)
    int ub = tid & 15;

    float wreg[32];
#pragma unroll
    for (int kk = 0; kk < 32; kk++)
        wreg[kk] = g_WhhT[(size_t)(ks * 32 + kk) * G4H + col];

    if (tid < 64) g_hbuf[1][bid * 64 + tid] = 0.0f;
    float creg = 0.0f;

    unsigned e = g_release + 1;   // stable: release only advances after ALL arrive
    grid_bar2(e, tid, bid);
    e++;

    for (int t = 0; t < TT; t++) {
        int rbuf = (t & 1) ^ 1;
        int wbuf = t & 1;

        // prefetch this step's 4 pregate values (independent of h)
        float pre[4];
        if (tid < 64) {
            size_t base = ((size_t)(ub * TT + t)) * G4H + bid * 4 + uj;
#pragma unroll
            for (int q = 0; q < 4; q++) pre[q] = g_pregates[base + q * 512];
        }

        // broadcast h into smem (32KB, coalesced float4)
        {
            const float4* src = (const float4*)g_hbuf[rbuf];
            float4* dst = (float4*)hs2;
#pragma unroll
            for (int i = 0; i < 8; i++) dst[tid + i * 256] = src[tid + i * 256];
        }
        __syncthreads();

        // partial gate GEMM: this thread: col, k in [ks*32, ks*32+32), all 16 batches
        ull acc[8];
#pragma unroll
        for (int p = 0; p < 8; p++) acc[p] = 0ULL;
#pragma unroll
        for (int kk = 0; kk < 32; kk++) {
            int k = ks * 32 + kk;
            float w = wreg[kk];
            ull w2 = packf2(w, w);
            const ulonglong2* hp = (const ulonglong2*)(hs2 + (size_t)k * 8);
            ulonglong2 h01 = hp[0];
            ulonglong2 h23 = hp[1];
            ulonglong2 h45 = hp[2];
            ulonglong2 h67 = hp[3];
            fma2(acc[0], h01.x, w2);
            fma2(acc[1], h01.y, w2);
            fma2(acc[2], h23.x, w2);
            fma2(acc[3], h23.y, w2);
            fma2(acc[4], h45.x, w2);
            fma2(acc[5], h45.y, w2);
            fma2(acc[6], h67.x, w2);
            fma2(acc[7], h67.y, w2);
        }
        {
            ull* pp = (ull*)&part_sm[c * 258 + ks * 16];
#pragma unroll
            for (int p = 0; p < 8; p++) pp[p] = acc[p];
        }
        __syncthreads();

        // merged reduce + activation + state update (64 threads)
        if (tid < 64) {
            float gv[4];
#pragma unroll
            for (int q = 0; q < 4; q++) {
                float s = pre[q];
                int base = (q * 4 + uj) * 258 + ub;
#pragma unroll
                for (int k2 = 0; k2 < 16; k2++)
                    s += part_sm[base + k2 * 16];
                gv[q] = s;
            }
            float ig = sigmoidf_(gv[0]);
            float fg = sigmoidf_(gv[1]);
            float gg = tanhf(gv[2]);
            float og = sigmoidf_(gv[3]);
            creg = fg * creg + ig * gg;
            float hn = og * tanhf(creg);
            int j = bid * 4 + uj;
            g_hbuf[wbuf][j * 16 + ub] = hn;
            g_combined[((size_t)(ub * TT + t)) * 768 + j] = hn;
        }

        if (t < TT - 1) {        // last step's h is read by nobody
            grid_bar2(e, tid, bid);
            e++;
        }
    }
}

// ---------------- softmax over memory slots (with cosine scaling) --------------
__global__ void __launch_bounds__(256) softmax_kernel() {
    __shared__ float red[256];
    __shared__ float s_kn;
    int p = blockIdx.x;          // 0..32767 (= (b*T+t)*4 + n)
    int tid = threadIdx.x;

    float kv = 0.0f;
    if (tid < DD) {
        float k = g_keys[(size_t)p * DD + tid];
        kv = k * k;
    }
    red[tid] = kv;
    __syncthreads();
    for (int o = 128; o > 0; o >>= 1) {
        if (tid < o) red[tid] += red[tid + o];
        __syncthreads();
    }
    if (tid == 0) s_kn = sqrtf(red[0]);
    __syncthreads();
    float kn = s_kn;
    __syncthreads();

    float v[8];
    float mx = -3.0e38f;
#pragma unroll
    for (int i = 0; i < 8; i++) {
        int m = tid + i * 256;
        float s = g_sims[(size_t)p * MM + m];
        s = s / fmaxf(kn * g_memnorm[m], EPSV);
        v[i] = s;
        mx = fmaxf(mx, s);
    }
    red[tid] = mx;
    __syncthreads();
    for (int o = 128; o > 0; o >>= 1) {
        if (tid < o) red[tid] = fmaxf(red[tid], red[tid + o]);
        __syncthreads();
    }
    mx = red[0];
    __syncthreads();

    float sum = 0.0f;
#pragma unroll
    for (int i = 0; i < 8; i++) {
        v[i] = __expf(v[i] - mx);
        sum += v[i];
    }
    red[tid] = sum;
    __syncthreads();
    for (int o = 128; o > 0; o >>= 1) {
        if (tid < o) red[tid] += red[tid + o];
        __syncthreads();
    }
    float inv = 1.0f / red[0];
#pragma unroll
    for (int i = 0; i < 8; i++) {
        int m = tid + i * 256;
        g_sims[(size_t)p * MM + m] = v[i] * inv;
    }
}

// ---------------- launch ----------------
extern "C" void kernel_launch(void* const* d_in, const int* in_sizes, int n_in,
                              void* d_out, int out_size) {
    const float* x      = (const float*)d_in[0];
    const float* memory = (const float*)d_in[1];
    const float* W_ih   = (const float*)d_in[2];
    const float* W_hh   = (const float*)d_in[3];
    const float* b_ih   = (const float*)d_in[4];
    const float* b_hh   = (const float*)d_in[5];
    const float* W_if   = (const float*)d_in[6];
    const float* b_if   = (const float*)d_in[7];
    const float* W_out  = (const float*)d_in[8];
    const float* b_out  = (const float*)d_in[9];
    float* out = (float*)d_out;

    float *pg, *comb, *keys, *sims;
    cudaGetSymbolAddress((void**)&pg, g_pregates);
    cudaGetSymbolAddress((void**)&comb, g_combined);
    cudaGetSymbolAddress((void**)&keys, g_keys);
    cudaGetSymbolAddress((void**)&sims, g_sims);

    // opt-in to >48KB dynamic smem for the LSTM kernel (attribute call, not an alloc)
    cudaFuncSetAttribute(lstm_kernel, cudaFuncAttributeMaxDynamicSharedMemorySize, LSTM_SMEM);

    // prep
    transpose_whh_kernel<<<(G4H * HH) / 256, 256>>>(W_hh);
    memnorm_kernel<<<MM, 64>>>(memory);

    // pre-gates: [8192,2048] = x[8192,256] @ W_ih^T + (b_ih + b_hh)
    tgemm<true, 128, false><<<dim3(G4H / 128, (BB * TT) / 128), 256>>>(
        x, W_ih, pg, BB * TT, G4H, II, II, II, G4H, b_ih, b_hh);

    // sequential LSTM recurrence (persistent, 1 flag-barrier/step)
    lstm_kernel<<<NBLK, 256, LSTM_SMEM>>>();

    // keys: [8192,256] = hs(combined[:, :512], lda=768) @ W_if[:256]^T + b_if[:256]
    tgemm<true, 128, false><<<dim3(256 / 128, (BB * TT) / 128), 256>>>(
        comb, W_if, keys, BB * TT, NHD * DD, HH, 768, HH, NHD * DD, b_if, nullptr);

    // sims: [32768,2048] = keys[32768,64] @ memory^T
    tgemm<true, 128, false><<<dim3(MM / 128, (BB * TT * NHD) / 128), 256>>>(
        keys, memory, sims, BB * TT * NHD, MM, DD, DD, DD, MM, nullptr, nullptr);

    // cosine-scale + softmax (in place on sims)
    softmax_kernel<<<BB * TT * NHD, 256>>>();

    // reads: attn[32768,2048] @ memory[2048,64], epilogue writes straight into
    // combined[r][512 + n*64 + d] via REMAP (row m = r*4+n)
    tgemm<false, 64, true><<<dim3(1, (BB * TT * NHD) / 128), 256>>>(
        sims, memory, comb, BB * TT * NHD, DD, MM, MM, DD, 0, nullptr, nullptr);

    // out: [8192,256] = combined[8192,768] @ W_out^T + b_out
    tgemm<true, 128, false><<<dim3(OO / 128, (BB * TT) / 128), 256>>>(
        comb, W_out, out, BB * TT, OO, HH + NHD * DD, 768, 768, OO, b_out, nullptr);
}

// round 13
// speedup vs baseline: 2.0297x; 1.1094x over previous
#include <cuda_runtime.h>
#include <cuda_bf16.h>
#include <math.h>

// Problem dims
#define BB 16
#define TT 512
#define II 256
#define HH 512
#define MM 2048
#define DD 64
#define NHD 4
#define OO 256
#define G4H 2048  // 4*H
#define EPSV 1e-8f

#define NBLK 128  // persistent LSTM grid (<= SM count -> co-resident)

// LSTM dynamic smem layout
#define HS2_BYTES  (HH * 8 * 8)        // 32768: h[k][b] as ull pairs
#define PART_BYTES (16 * 258 * 4)      // 16512: partials, padded stride
#define LSTM_SMEM  (HS2_BYTES + PART_BYTES)  // 49280 (> 48KB static -> dynamic)

// Fused-attention smem layout (all unsigned/float words)
#define KA_OFF   0                         // Ka  [64][132] u32 (K tile, [k][row])
#define MS_OFF   (KA_OFF  + 64*132*4)      // Ms  [64][132] u32 (Mem, [d][slot])
#define MS2_OFF  (MS_OFF  + 64*132*4)      // Ms2 [128][68] u32 (Mem, [slot][d])
#define PS_OFF   (MS2_OFF + 128*68*4)      // Ps  [128][132] u32 (P, [slot][row])
#define IKN_OFF  (PS_OFF  + 128*132*4)     // float[128]
#define IMN_OFF  (IKN_OFF + 512)           // float[128]
#define LROW_OFF (IMN_OFF + 512)           // float[128]
#define LP_OFF   (LROW_OFF + 512)          // float[2][128]
#define ATT_SMEM (LP_OFF + 1024)           // = 172544

typedef unsigned long long ull;

// ---------------- scratch (static device globals; no runtime alloc) ------------
__device__ float g_pregates[(size_t)BB * TT * G4H];   // 64 MB, row r = b*T+t
__device__ float g_hbuf[2][HH * BB];                  // [buf][k*16+b], double buffered
__device__ float g_combined[(size_t)BB * TT * (HH + NHD * DD)];  // [8192][768]
__device__ float g_keys[(size_t)BB * TT * NHD * DD];  // [32768][64]
__device__ float g_WhhT[HH * G4H];                    // [512][2048]
__device__ float g_memnorm[MM];
__device__ volatile unsigned g_arrive[NBLK];          // flag barrier: per-block arrival
__device__ volatile unsigned g_release;               // flag barrier: release epoch

// ---------------- helpers ----------------
__device__ __forceinline__ float sigmoidf_(float x) {
    return 1.0f / (1.0f + __expf(-x));
}

__device__ __forceinline__ ull packf2(float a, float b) {
    ull r;
    asm("mov.b64 %0, {%1, %2};" : "=l"(r) : "f"(a), "f"(b));
    return r;
}
__device__ __forceinline__ void fma2(ull& d, ull a, ull b) {
    asm("fma.rn.f32x2 %0, %1, %2, %0;" : "+l"(d) : "l"(a), "l"(b));
}

__device__ __forceinline__ unsigned f2tf(float f) {
    unsigned r;
    asm("cvt.rna.tf32.f32 %0, %1;" : "=r"(r) : "f"(f));
    return r;
}

__device__ __forceinline__ void mma_tf32(float* c, const unsigned* a, const unsigned* b) {
    asm volatile(
        "mma.sync.aligned.m16n8k8.row.col.f32.tf32.tf32.f32 "
        "{%0,%1,%2,%3}, {%4,%5,%6,%7}, {%8,%9}, {%0,%1,%2,%3};"
        : "+f"(c[0]), "+f"(c[1]), "+f"(c[2]), "+f"(c[3])
        : "r"(a[0]), "r"(a[1]), "r"(a[2]), "r"(a[3]), "r"(b[0]), "r"(b[1]));
}

// Flag-based grid barrier (R9-measured design).
__device__ __forceinline__ void grid_bar2(unsigned e, int tid, int bid) {
    __syncthreads();
    if (tid == 0) {
        __threadfence();              // publish this block's global writes
        g_arrive[bid] = e;
    }
    if (bid == 0) {
        if (tid < NBLK) {
            while (g_arrive[tid] != e) { }
        }
        __syncthreads();
        if (tid == 0) g_release = e;
    } else {
        if (tid == 0) {
            while (g_release != e) { }
        }
    }
    if (tid == 0) __threadfence();    // acquire side: flush/invalidate L1
    __syncthreads();
}

// ---------------- small prep kernels ----------------
__global__ void transpose_whh_kernel(const float* __restrict__ W_hh) {
    int idx = blockIdx.x * 256 + threadIdx.x;  // total 2048*512
    int g = idx & (G4H - 1);
    int k = idx >> 11;
    g_WhhT[k * G4H + g] = W_hh[g * HH + k];
}

__global__ void memnorm_kernel(const float* __restrict__ memory) {
    __shared__ float s[64];
    int m = blockIdx.x;
    float v = memory[m * DD + threadIdx.x];
    s[threadIdx.x] = v * v;
    __syncthreads();
    for (int o = 32; o > 0; o >>= 1) {
        if (threadIdx.x < o) s[threadIdx.x] += s[threadIdx.x + o];
        __syncthreads();
    }
    if (threadIdx.x == 0) g_memnorm[m] = sqrtf(s[0]);
}

// ---------------- tf32 tensor-core GEMM ----------------
// C[m][n] = sum_k A[m*lda+k] * (BT ? B[n*ldb+k] : B[k*ldb+n]) + bias1[n] + bias2[n]
template <bool BT, int BN, bool REMAP>
__global__ void __launch_bounds__(256) tgemm(
    const float* __restrict__ A, const float* __restrict__ B, float* __restrict__ C,
    int M, int N, int K, int lda, int ldb, int ldc,
    const float* __restrict__ bias1, const float* __restrict__ bias2)
{
    constexpr int WN = BN / 2;
    constexpr int NT = WN / 8;
    __shared__ unsigned As[2][16][132];
    __shared__ unsigned Bs[2][16][BN + 4];

    int tid = threadIdx.x;
    int wid = tid >> 5, lane = tid & 31;
    int wm = (wid >> 1) * 32;
    int wn = (wid & 1) * WN;
    int m0 = blockIdx.y * 128;
    int n0 = blockIdx.x * BN;
    int g = lane >> 2, tg = lane & 3;

    float acc[2][NT][4];
#pragma unroll
    for (int i = 0; i < 2; i++)
#pragma unroll
        for (int j = 0; j < NT; j++)
#pragma unroll
            for (int e = 0; e < 4; e++) acc[i][j][e] = 0.0f;

    int a_r = tid >> 1;
    int ak = (tid & 1) * 8;
    const float* Aptr = A + (size_t)(m0 + a_r) * lda + ak;

    const float* Bptr;
    int bn4 = 0, bk_nn = 0;
    if (BT) {
        Bptr = B + (size_t)(n0 + a_r) * ldb + ak;
    } else {
        bk_nn = tid >> 4;
        bn4 = (tid & 15) * 4;
        Bptr = B + (size_t)bk_nn * ldb + n0 + bn4;
    }

    int KT = K >> 4;

    {
        float4 a0 = *(const float4*)Aptr;
        float4 a1 = *(const float4*)(Aptr + 4);
        As[0][ak + 0][a_r] = f2tf(a0.x); As[0][ak + 1][a_r] = f2tf(a0.y);
        As[0][ak + 2][a_r] = f2tf(a0.z); As[0][ak + 3][a_r] = f2tf(a0.w);
        As[0][ak + 4][a_r] = f2tf(a1.x); As[0][ak + 5][a_r] = f2tf(a1.y);
        As[0][ak + 6][a_r] = f2tf(a1.z); As[0][ak + 7][a_r] = f2tf(a1.w);
        if (BT) {
            float4 b0 = *(const float4*)Bptr;
            float4 b1 = *(const float4*)(Bptr + 4);
            Bs[0][ak + 0][a_r] = f2tf(b0.x); Bs[0][ak + 1][a_r] = f2tf(b0.y);
            Bs[0][ak + 2][a_r] = f2tf(b0.z); Bs[0][ak + 3][a_r] = f2tf(b0.w);
            Bs[0][ak + 4][a_r] = f2tf(b1.x); Bs[0][ak + 5][a_r] = f2tf(b1.y);
            Bs[0][ak + 6][a_r] = f2tf(b1.z); Bs[0][ak + 7][a_r] = f2tf(b1.w);
        } else {
            float4 b0 = *(const float4*)Bptr;
            Bs[0][bk_nn][bn4 + 0] = f2tf(b0.x); Bs[0][bk_nn][bn4 + 1] = f2tf(b0.y);
            Bs[0][bk_nn][bn4 + 2] = f2tf(b0.z); Bs[0][bk_nn][bn4 + 3] = f2tf(b0.w);
        }
    }
    __syncthreads();

    for (int kt = 0; kt < KT; kt++) {
        int cur = kt & 1;
        float4 pa0, pa1, pb0, pb1;
        bool has_next = (kt + 1 < KT);
        if (has_next) {
            pa0 = *(const float4*)(Aptr + (kt + 1) * 16);
            pa1 = *(const float4*)(Aptr + (kt + 1) * 16 + 4);
            if (BT) {
                pb0 = *(const float4*)(Bptr + (kt + 1) * 16);
                pb1 = *(const float4*)(Bptr + (kt + 1) * 16 + 4);
            } else {
                pb0 = *(const float4*)(Bptr + (size_t)(kt + 1) * 16 * ldb);
            }
        }

#pragma unroll
        for (int ks = 0; ks < 2; ks++) {
            int kb = ks * 8;
            unsigned af[2][4];
#pragma unroll
            for (int mt = 0; mt < 2; mt++) {
                int row = wm + mt * 16;
                af[mt][0] = As[cur][kb + tg][row + g];
                af[mt][1] = As[cur][kb + tg][row + g + 8];
                af[mt][2] = As[cur][kb + tg + 4][row + g];
                af[mt][3] = As[cur][kb + tg + 4][row + g + 8];
            }
            unsigned bf[NT][2];
#pragma unroll
            for (int nt = 0; nt < NT; nt++) {
                bf[nt][0] = Bs[cur][kb + tg][wn + nt * 8 + g];
                bf[nt][1] = Bs[cur][kb + tg + 4][wn + nt * 8 + g];
            }
#pragma unroll
            for (int mt = 0; mt < 2; mt++)
#pragma unroll
                for (int nt = 0; nt < NT; nt++)
                    mma_tf32(acc[mt][nt], af[mt], bf[nt]);
        }

        if (has_next) {
            int nxt = cur ^ 1;
            As[nxt][ak + 0][a_r] = f2tf(pa0.x); As[nxt][ak + 1][a_r] = f2tf(pa0.y);
            As[nxt][ak + 2][a_r] = f2tf(pa0.z); As[nxt][ak + 3][a_r] = f2tf(pa0.w);
            As[nxt][ak + 4][a_r] = f2tf(pa1.x); As[nxt][ak + 5][a_r] = f2tf(pa1.y);
            As[nxt][ak + 6][a_r] = f2tf(pa1.z); As[nxt][ak + 7][a_r] = f2tf(pa1.w);
            if (BT) {
                Bs[nxt][ak + 0][a_r] = f2tf(pb0.x); Bs[nxt][ak + 1][a_r] = f2tf(pb0.y);
                Bs[nxt][ak + 2][a_r] = f2tf(pb0.z); Bs[nxt][ak + 3][a_r] = f2tf(pb0.w);
                Bs[nxt][ak + 4][a_r] = f2tf(pb1.x); Bs[nxt][ak + 5][a_r] = f2tf(pb1.y);
                Bs[nxt][ak + 6][a_r] = f2tf(pb1.z); Bs[nxt][ak + 7][a_r] = f2tf(pb1.w);
            } else {
                Bs[nxt][bk_nn][bn4 + 0] = f2tf(pb0.x); Bs[nxt][bk_nn][bn4 + 1] = f2tf(pb0.y);
                Bs[nxt][bk_nn][bn4 + 2] = f2tf(pb0.z); Bs[nxt][bk_nn][bn4 + 3] = f2tf(pb0.w);
            }
            __syncthreads();
        }
    }

#pragma unroll
    for (int mt = 0; mt < 2; mt++) {
        int r0 = m0 + wm + mt * 16 + g;
#pragma unroll
        for (int nt = 0; nt < NT; nt++) {
            int cc = n0 + wn + nt * 8 + tg * 2;
            float bv0 = 0.0f, bv1 = 0.0f;
            if (bias1) { bv0 += bias1[cc]; bv1 += bias1[cc + 1]; }
            if (bias2) { bv0 += bias2[cc]; bv1 += bias2[cc + 1]; }
            float2 v0 = make_float2(acc[mt][nt][0] + bv0, acc[mt][nt][1] + bv1);
            float2 v1 = make_float2(acc[mt][nt][2] + bv0, acc[mt][nt][3] + bv1);
            if (REMAP) {
                int ra = r0, rb2 = r0 + 8;
                size_t o0 = (size_t)(ra >> 2) * 768 + 512 + (ra & 3) * 64 + cc;
                size_t o1 = (size_t)(rb2 >> 2) * 768 + 512 + (rb2 & 3) * 64 + cc;
                *(float2*)&C[o0] = v0;
                *(float2*)&C[o1] = v1;
            } else {
                *(float2*)&C[(size_t)r0 * ldc + cc] = v0;
                *(float2*)&C[(size_t)(r0 + 8) * ldc + cc] = v1;
            }
        }
    }
}

// ---------------- fused attention kernel ----------------
// Per block: 128 key-rows (p = blockIdx*128 ..). Loops 16 memory tiles of 128
// slots. S = K@M^T (tf32 mma), p = exp(S * ikn[r] * imn[m]) (cos in [-1,1], no
// max needed), l += rowsum(p) (deterministic two-warp partials, summed from the
// tf32-rounded p), O += P@M (P round-trips smem as tf32). Epilogue: O/l written
// straight into combined[p>>2][512 + (p&3)*64 + d].
__global__ void __launch_bounds__(256) attn_kernel(const float* __restrict__ memory) {
    extern __shared__ __align__(16) char sm[];
    unsigned (*Ka)[132]  = (unsigned(*)[132])(sm + KA_OFF);
    unsigned (*Ms)[132]  = (unsigned(*)[132])(sm + MS_OFF);
    unsigned (*Ms2)[68]  = (unsigned(*)[68])(sm + MS2_OFF);
    unsigned (*Ps)[132]  = (unsigned(*)[132])(sm + PS_OFF);
    float* ikn  = (float*)(sm + IKN_OFF);
    float* imn  = (float*)(sm + IMN_OFF);
    float* lrow = (float*)(sm + LROW_OFF);
    float (*lpart)[128] = (float(*)[128])(sm + LP_OFF);

    int tid = threadIdx.x;
    int wid = tid >> 5, lane = tid & 31;
    int g = lane >> 2, tg = lane & 3;
    int wm = (wid >> 1) * 32;
    int wn = (wid & 1) * 64;     // S n-half (128 cols)
    int wn2 = (wid & 1) * 32;    // O n-half (64 cols)
    int pbase = blockIdx.x * 128;

    // load K tile [128 rows][64 d] -> Ka[k][row] (tf32) + row inverse norms
    {
        int row = tid >> 1;
        int f0 = (tid & 1) * 8;
        const float4* src = (const float4*)(g_keys + (size_t)(pbase + row) * DD) + f0;
        float ss = 0.0f;
#pragma unroll
        for (int i = 0; i < 8; i++) {
            float4 v = src[i];
            int k0 = (f0 + i) * 4;
            Ka[k0 + 0][row] = f2tf(v.x); Ka[k0 + 1][row] = f2tf(v.y);
            Ka[k0 + 2][row] = f2tf(v.z); Ka[k0 + 3][row] = f2tf(v.w);
            ss += v.x * v.x + v.y * v.y + v.z * v.z + v.w * v.w;
        }
        ss += __shfl_xor_sync(0xffffffffu, ss, 1);
        if ((tid & 1) == 0) ikn[row] = rsqrtf(ss);
        if (tid < 128) lrow[tid] = 0.0f;
    }

    float o[2][4][4];
#pragma unroll
    for (int mt = 0; mt < 2; mt++)
#pragma unroll
        for (int nt = 0; nt < 4; nt++)
#pragma unroll
            for (int e = 0; e < 4; e++) o[mt][nt][e] = 0.0f;

    for (int m0t = 0; m0t < MM; m0t += 128) {
        __syncthreads();   // prev P-mma done reading Ms2/Ps (no-op first iter)

        // load memory tile 128 slots x 64 d -> Ms[d][slot] and Ms2[slot][d]
        {
            int slot = tid >> 1;
            int f0 = (tid & 1) * 8;
            const float4* src = (const float4*)(memory + (size_t)(m0t + slot) * DD) + f0;
#pragma unroll
            for (int i = 0; i < 8; i++) {
                float4 v = src[i];
                int k0 = (f0 + i) * 4;
                unsigned ua = f2tf(v.x), ub = f2tf(v.y), uc = f2tf(v.z), ud = f2tf(v.w);
                Ms[k0 + 0][slot] = ua; Ms[k0 + 1][slot] = ub;
                Ms[k0 + 2][slot] = uc; Ms[k0 + 3][slot] = ud;
                Ms2[slot][k0 + 0] = ua; Ms2[slot][k0 + 1] = ub;
                Ms2[slot][k0 + 2] = uc; Ms2[slot][k0 + 3] = ud;
            }
            if (tid < 128) imn[tid] = 1.0f / g_memnorm[m0t + tid];
        }
        __syncthreads();

        // S = K @ Mtile^T : 128x128, k=64
        float s[2][8][4];
#pragma unroll
        for (int mt = 0; mt < 2; mt++)
#pragma unroll
            for (int nt = 0; nt < 8; nt++)
#pragma unroll
                for (int e = 0; e < 4; e++) s[mt][nt][e] = 0.0f;
#pragma unroll
        for (int kb = 0; kb < 64; kb += 8) {
            unsigned af[2][4];
#pragma unroll
            for (int mt = 0; mt < 2; mt++) {
                int row = wm + mt * 16;
                af[mt][0] = Ka[kb + tg][row + g];
                af[mt][1] = Ka[kb + tg][row + g + 8];
                af[mt][2] = Ka[kb + tg + 4][row + g];
                af[mt][3] = Ka[kb + tg + 4][row + g + 8];
            }
            unsigned bf[8][2];
#pragma unroll
            for (int nt = 0; nt < 8; nt++) {
                bf[nt][0] = Ms[kb + tg][wn + nt * 8 + g];
                bf[nt][1] = Ms[kb + tg + 4][wn + nt * 8 + g];
            }
#pragma unroll
            for (int mt = 0; mt < 2; mt++)
#pragma unroll
                for (int nt = 0; nt < 8; nt++)
                    mma_tf32(s[mt][nt], af[mt], bf[nt]);
        }

        // exp + Ps (tf32) + deterministic row-sum partials
        float lp[4] = {0.0f, 0.0f, 0.0f, 0.0f};
#pragma unroll
        for (int mt = 0; mt < 2; mt++) {
            int r0 = wm + mt * 16 + g;
            float ka0 = ikn[r0], ka1 = ikn[r0 + 8];
#pragma unroll
            for (int nt = 0; nt < 8; nt++) {
                int c0 = wn + nt * 8 + tg * 2;
                float im0 = imn[c0], im1 = imn[c0 + 1];
                unsigned u00 = f2tf(__expf(s[mt][nt][0] * ka0 * im0));
                unsigned u01 = f2tf(__expf(s[mt][nt][1] * ka0 * im1));
                unsigned u10 = f2tf(__expf(s[mt][nt][2] * ka1 * im0));
                unsigned u11 = f2tf(__expf(s[mt][nt][3] * ka1 * im1));
                lp[mt * 2 + 0] += __uint_as_float(u00) + __uint_as_float(u01);
                lp[mt * 2 + 1] += __uint_as_float(u10) + __uint_as_float(u11);
                Ps[c0][r0] = u00;     Ps[c0 + 1][r0] = u01;
                Ps[c0][r0 + 8] = u10; Ps[c0 + 1][r0 + 8] = u11;
            }
        }
#pragma unroll
        for (int q = 0; q < 4; q++) {
            lp[q] += __shfl_xor_sync(0xffffffffu, lp[q], 1);
            lp[q] += __shfl_xor_sync(0xffffffffu, lp[q], 2);
        }
        if (tg == 0) {
#pragma unroll
            for (int mt = 0; mt < 2; mt++) {
                lpart[wid & 1][wm + mt * 16 + g] = lp[mt * 2 + 0];
                lpart[wid & 1][wm + mt * 16 + g + 8] = lp[mt * 2 + 1];
            }
        }
        __syncthreads();

        if (tid < 128) lrow[tid] += lpart[0][tid] + lpart[1][tid];

        // O += P @ Mtile : 128x64, k=128
#pragma unroll 4
        for (int kb = 0; kb < 128; kb += 8) {
            unsigned af[2][4];
#pragma unroll
            for (int mt = 0; mt < 2; mt++) {
                int row = wm + mt * 16;
                af[mt][0] = Ps[kb + tg][row + g];
                af[mt][1] = Ps[kb + tg][row + g + 8];
                af[mt][2] = Ps[kb + tg + 4][row + g];
                af[mt][3] = Ps[kb + tg + 4][row + g + 8];
            }
            unsigned bf[4][2];
#pragma unroll
            for (int nt = 0; nt < 4; nt++) {
                bf[nt][0] = Ms2[kb + tg][wn2 + nt * 8 + g];
                bf[nt][1] = Ms2[kb + tg + 4][wn2 + nt * 8 + g];
            }
#pragma unroll
            for (int mt = 0; mt < 2; mt++)
#pragma unroll
                for (int nt = 0; nt < 4; nt++)
                    mma_tf32(o[mt][nt], af[mt], bf[nt]);
        }
    }

    __syncthreads();   // lrow final

    // epilogue: reads = O / l -> combined[p>>2][512 + (p&3)*64 + d]
#pragma unroll
    for (int mt = 0; mt < 2; mt++) {
        int r0 = wm + mt * 16 + g;
        float il0 = 1.0f / lrow[r0];
        float il1 = 1.0f / lrow[r0 + 8];
        int p0 = pbase + r0;
        int p1 = p0 + 8;
        size_t b0 = (size_t)(p0 >> 2) * 768 + 512 + (p0 & 3) * 64;
        size_t b1 = (size_t)(p1 >> 2) * 768 + 512 + (p1 & 3) * 64;
#pragma unroll
        for (int nt = 0; nt < 4; nt++) {
            int cc = wn2 + nt * 8 + tg * 2;
            float2 v0 = make_float2(o[mt][nt][0] * il0, o[mt][nt][1] * il0);
            float2 v1 = make_float2(o[mt][nt][2] * il1, o[mt][nt][3] * il1);
            *(float2*)&g_combined[b0 + cc] = v0;
            *(float2*)&g_combined[b1 + cc] = v1;
        }
    }
}

// ---------------- persistent LSTM kernel ----------------
__global__ void __launch_bounds__(256) lstm_kernel() {
    extern __shared__ __align__(16) char dynsm[];
    ull*   hs2     = (ull*)dynsm;                              // h[k][b] pairs, 32KB
    float* part_sm = (float*)(dynsm + HS2_BYTES);              // [c][ks*16+b], stride 258

    int tid = threadIdx.x;
    int bid = blockIdx.x;

    int ks = tid >> 4;
    int c  = tid & 15;
    int col = (c >> 2) * 512 + bid * 4 + (c & 3);

    int uj = tid >> 4;
    int ub = tid & 15;

    float wreg[32];
#pragma unroll
    for (int kk = 0; kk < 32; kk++)
        wreg[kk] = g_WhhT[(size_t)(ks * 32 + kk) * G4H + col];

    if (tid < 64) g_hbuf[1][bid * 64 + tid] = 0.0f;
    float creg = 0.0f;

    unsigned e = g_release + 1;
    grid_bar2(e, tid, bid);
    e++;

    for (int t = 0; t < TT; t++) {
        int rbuf = (t & 1) ^ 1;
        int wbuf = t & 1;

        float pre[4];
        if (tid < 64) {
            size_t base = ((size_t)(ub * TT + t)) * G4H + bid * 4 + uj;
#pragma unroll
            for (int q = 0; q < 4; q++) pre[q] = g_pregates[base + q * 512];
        }

        {
            const float4* src = (const float4*)g_hbuf[rbuf];
            float4* dst = (float4*)hs2;
#pragma unroll
            for (int i = 0; i < 8; i++) dst[tid + i * 256] = src[tid + i * 256];
        }
        __syncthreads();

        ull acc[8];
#pragma unroll
        for (int p = 0; p < 8; p++) acc[p] = 0ULL;
#pragma unroll
        for (int kk = 0; kk < 32; kk++) {
            int k = ks * 32 + kk;
            float w = wreg[kk];
            ull w2 = packf2(w, w);
            const ulonglong2* hp = (const ulonglong2*)(hs2 + (size_t)k * 8);
            ulonglong2 h01 = hp[0];
            ulonglong2 h23 = hp[1];
            ulonglong2 h45 = hp[2];
            ulonglong2 h67 = hp[3];
            fma2(acc[0], h01.x, w2);
            fma2(acc[1], h01.y, w2);
            fma2(acc[2], h23.x, w2);
            fma2(acc[3], h23.y, w2);
            fma2(acc[4], h45.x, w2);
            fma2(acc[5], h45.y, w2);
            fma2(acc[6], h67.x, w2);
            fma2(acc[7], h67.y, w2);
        }
        {
            ull* pp = (ull*)&part_sm[c * 258 + ks * 16];
#pragma unroll
            for (int p = 0; p < 8; p++) pp[p] = acc[p];
        }
        __syncthreads();

        if (tid < 64) {
            float gv[4];
#pragma unroll
            for (int q = 0; q < 4; q++) {
                float s = pre[q];
                int base = (q * 4 + uj) * 258 + ub;
#pragma unroll
                for (int k2 = 0; k2 < 16; k2++)
                    s += part_sm[base + k2 * 16];
                gv[q] = s;
            }
            float ig = sigmoidf_(gv[0]);
            float fg = sigmoidf_(gv[1]);
            float gg = tanhf(gv[2]);
            float og = sigmoidf_(gv[3]);
            creg = fg * creg + ig * gg;
            float hn = og * tanhf(creg);
            int j = bid * 4 + uj;
            g_hbuf[wbuf][j * 16 + ub] = hn;
            g_combined[((size_t)(ub * TT + t)) * 768 + j] = hn;
        }

        if (t < TT - 1) {
            grid_bar2(e, tid, bid);
            e++;
        }
    }
}

// ---------------- launch ----------------
extern "C" void kernel_launch(void* const* d_in, const int* in_sizes, int n_in,
                              void* d_out, int out_size) {
    const float* x      = (const float*)d_in[0];
    const float* memory = (const float*)d_in[1];
    const float* W_ih   = (const float*)d_in[2];
    const float* W_hh   = (const float*)d_in[3];
    const float* b_ih   = (const float*)d_in[4];
    const float* b_hh   = (const float*)d_in[5];
    const float* W_if   = (const float*)d_in[6];
    const float* b_if   = (const float*)d_in[7];
    const float* W_out  = (const float*)d_in[8];
    const float* b_out  = (const float*)d_in[9];
    float* out = (float*)d_out;

    float *pg, *comb, *keys;
    cudaGetSymbolAddress((void**)&pg, g_pregates);
    cudaGetSymbolAddress((void**)&comb, g_combined);
    cudaGetSymbolAddress((void**)&keys, g_keys);

    // opt-in to large dynamic smem (attribute calls, not allocations)
    cudaFuncSetAttribute(lstm_kernel, cudaFuncAttributeMaxDynamicSharedMemorySize, LSTM_SMEM);
    cudaFuncSetAttribute(attn_kernel, cudaFuncAttributeMaxDynamicSharedMemorySize, ATT_SMEM);

    // prep
    transpose_whh_kernel<<<(G4H * HH) / 256, 256>>>(W_hh);
    memnorm_kernel<<<MM, 64>>>(memory);

    // pre-gates: [8192,2048] = x[8192,256] @ W_ih^T + (b_ih + b_hh)
    tgemm<true, 128, false><<<dim3(G4H / 128, (BB * TT) / 128), 256>>>(
        x, W_ih, pg, BB * TT, G4H, II, II, II, G4H, b_ih, b_hh);

    // sequential LSTM recurrence (persistent, 1 flag-barrier/step)
    lstm_kernel<<<NBLK, 256, LSTM_SMEM>>>();

    // keys: [8192,256] = hs(combined[:, :512], lda=768) @ W_if[:256]^T + b_if[:256]
    tgemm<true, 128, false><<<dim3(256 / 128, (BB * TT) / 128), 256>>>(
        comb, W_if, keys, BB * TT, NHD * DD, HH, 768, HH, NHD * DD, b_if, nullptr);

    // fused attention: sims + softmax + reads in one kernel, writes combined[:,512:]
    attn_kernel<<<(BB * TT * NHD) / 128, 256, ATT_SMEM>>>(memory);

    // out: [8192,256] = combined[8192,768] @ W_out^T + b_out
    tgemm<true, 128, false><<<dim3(OO / 128, (BB * TT) / 128), 256>>>(
        comb, W_out, out, BB * TT, OO, HH + NHD * DD, 768, 768, OO, b_out, nullptr);
}